// round 5
// baseline (speedup 1.0000x reference)
#include <cuda_runtime.h>
#include <cstdint>

// Problem dims
#define TT   2048
#define BB   8
#define II   512
#define HH   512
#define G4H  2048
#define MTOT (BB*TT)     // 16384

// Recurrence persistent-kernel config
#define NCTA      128    // 2 dirs * 64 CTAs; 8 h-units per CTA
#define RTHREADS  256

// ---------------- static device scratch (no allocations allowed) ----------------
// Precomputed input-gate projections: G[dir][m][4H], m = b*T + t  (256 MiB)
__device__ __align__(16) float g_G[(size_t)2 * MTOT * G4H];
// Hidden state ping buffer: h[dir][b][H]
__device__ __align__(16) float g_h[2 * BB * HH];
// Grid barrier state
__device__ unsigned g_cnt;
__device__ unsigned g_gen;

// =================================================================================
// Kernel 1: gates GEMM.  G[dir][m][n] = sum_k X[m][k]*Wih_dir[n][k] + bih[n]+bhh[n]
// Tiles: BM=128, BN=128, BK=8, 256 threads, 8x8 per thread.
// =================================================================================
__global__ __launch_bounds__(256) void gates_gemm(
    const float* __restrict__ X,
    const float* __restrict__ Wf, const float* __restrict__ bif, const float* __restrict__ bhf,
    const float* __restrict__ Wb, const float* __restrict__ bib, const float* __restrict__ bhb)
{
    const int dir = blockIdx.z;
    const float* __restrict__ W  = dir ? Wb  : Wf;
    const float* __restrict__ b1 = dir ? bib : bif;
    const float* __restrict__ b2 = dir ? bhb : bhf;

    __shared__ __align__(16) float As[8][128];
    __shared__ __align__(16) float Bs[8][128];

    const int tid  = threadIdx.x;
    const int m0   = blockIdx.y * 128;
    const int n0   = blockIdx.x * 128;
    const int tx   = tid & 15;          // n-frag
    const int ty   = tid >> 4;          // m-frag
    const int lrow = tid >> 1;          // 0..127
    const int lk   = (tid & 1) * 4;     // 0 or 4

    float acc[8][8];
#pragma unroll
    for (int i = 0; i < 8; i++)
#pragma unroll
        for (int j = 0; j < 8; j++) acc[i][j] = 0.f;

    const float* Ag = X + (size_t)(m0 + lrow) * II + lk;
    const float* Bg = W + (size_t)(n0 + lrow) * II + lk;

    float4 a = *(const float4*)(Ag);
    float4 b = *(const float4*)(Bg);

    for (int k0 = 0; k0 < II; k0 += 8) {
        __syncthreads();
        As[lk + 0][lrow] = a.x; As[lk + 1][lrow] = a.y;
        As[lk + 2][lrow] = a.z; As[lk + 3][lrow] = a.w;
        Bs[lk + 0][lrow] = b.x; Bs[lk + 1][lrow] = b.y;
        Bs[lk + 2][lrow] = b.z; Bs[lk + 3][lrow] = b.w;
        __syncthreads();
        if (k0 + 8 < II) {
            a = *(const float4*)(Ag + k0 + 8);
            b = *(const float4*)(Bg + k0 + 8);
        }
#pragma unroll
        for (int k = 0; k < 8; k++) {
            float4 a0 = *(const float4*)&As[k][ty * 8];
            float4 a1 = *(const float4*)&As[k][ty * 8 + 4];
            float4 b0 = *(const float4*)&Bs[k][tx * 8];
            float4 b1v = *(const float4*)&Bs[k][tx * 8 + 4];
            float ar[8] = {a0.x, a0.y, a0.z, a0.w, a1.x, a1.y, a1.z, a1.w};
            float br[8] = {b0.x, b0.y, b0.z, b0.w, b1v.x, b1v.y, b1v.z, b1v.w};
#pragma unroll
            for (int i = 0; i < 8; i++)
#pragma unroll
                for (int j = 0; j < 8; j++)
                    acc[i][j] = fmaf(ar[i], br[j], acc[i][j]);
        }
    }

    const int nb = n0 + tx * 8;
    float bias[8];
#pragma unroll
    for (int j = 0; j < 8; j++) bias[j] = b1[nb + j] + b2[nb + j];

#pragma unroll
    for (int i = 0; i < 8; i++) {
        size_t row = (size_t)dir * MTOT + (size_t)(m0 + ty * 8 + i);
        float* op = g_G + row * G4H + nb;
        float4 o0, o1;
        o0.x = acc[i][0] + bias[0]; o0.y = acc[i][1] + bias[1];
        o0.z = acc[i][2] + bias[2]; o0.w = acc[i][3] + bias[3];
        o1.x = acc[i][4] + bias[4]; o1.y = acc[i][5] + bias[5];
        o1.z = acc[i][6] + bias[6]; o1.w = acc[i][7] + bias[7];
        *(float4*)op = o0;
        *(float4*)(op + 4) = o1;
    }
}

// =================================================================================
// Kernel 2: persistent bidirectional LSTM recurrence.
// 128 CTAs: CTA (dir, hblk) owns 8 h-units (all 4 gate rows each) of one direction.
// Whh slice (32 rows x 512) lives in SMEM for the whole kernel.
// Per step: stage h (16KB), 256 threads each compute a 4-gate x 8-batch x 16-K
// partial (K split 32 ways), tree-reduce via padded SMEM, 64 threads do the
// cell update + write h, grid barrier.
// =================================================================================
__device__ __forceinline__ float sigm_f(float x) {
    return __fdividef(1.f, 1.f + __expf(-x));
}
__device__ __forceinline__ float tanh_f(float x) {
    float ax = fabsf(x);
    float e  = __expf(-2.f * ax);               // in (0,1], never overflows
    float r  = __fdividef(1.f - e, 1.f + e);
    return x < 0.f ? -r : r;
}

#define SM_W   0                   // 32*512 floats
#define SM_H   16384               // 8*512 floats
#define SM_RED 20480               // 256*33 floats
#define SM_FLOATS (SM_RED + 256*33)

__global__ __launch_bounds__(RTHREADS, 1) void lstm_recur(
    const float* __restrict__ Whh_f,
    const float* __restrict__ Whh_b,
    float* __restrict__ out)
{
    extern __shared__ __align__(16) float smem[];
    float* Wsm = smem + SM_W;
    float* Hsm = smem + SM_H;
    float* Red = smem + SM_RED;

    const int tid = threadIdx.x;
    const int cta = blockIdx.x;
    const int dir = cta >> 6;
    const int h0  = (cta & 63) * 8;
    const float* __restrict__ Whh = dir ? Whh_b : Whh_f;

    // ---- one-time weight load: smem row (u*4+g) <- Whh row (g*512 + h0 + u) ----
#pragma unroll
    for (int v = 0; v < 16; v++) {
        int q = tid + v * 256;          // float4 index 0..4095
        int r = q >> 7;                 // smem row 0..31
        int u = r >> 2, g = r & 3;
        int grow = g * HH + h0 + u;
        *(float4*)&Wsm[q * 4] =
            *(const float4*)&Whh[(size_t)grow * HH + (size_t)(q & 127) * 4];
    }
    __syncthreads();

    const int u_w = tid >> 5;     // dot-product unit (== warp id), 0..7
    const int ks  = tid & 31;     // K-slice lane
    const int u_a = tid >> 3;     // activation unit (tid<64), 0..7
    const int b_a = tid & 7;      // activation batch
    const int hg  = h0 + u_a;     // global h index for activation thread

    float c = 0.f;                // cell state for (u_a, b_a), tid<64 only

    for (int step = 0; step < TT; step++) {
        const int t_eff = dir ? (TT - 1 - step) : step;

        // prefetch precomputed input gates (latency hidden by the dot loop)
        float Gv[4];
        if (tid < 64) {
            const float* gp = g_G +
                ((size_t)(dir * MTOT + b_a * TT + t_eff)) * G4H + hg;
            Gv[0] = __ldg(gp);
            Gv[1] = __ldg(gp + 512);
            Gv[2] = __ldg(gp + 1024);
            Gv[3] = __ldg(gp + 1536);
        }

        if (step > 0) {
            // stage h[dir] (8x512 floats) into SMEM, coalesced float4
            const float* hp = g_h + dir * (BB * HH);
#pragma unroll
            for (int v = 0; v < 4; v++) {
                int q = tid + v * 256;  // float4 index 0..1023
                *(float4*)&Hsm[q * 4] = *(const float4*)&hp[q * 4];
            }
        }
        __syncthreads();

        if (step > 0) {
            float acc[4][8];
#pragma unroll
            for (int g = 0; g < 4; g++)
#pragma unroll
                for (int b = 0; b < 8; b++) acc[g][b] = 0.f;

#pragma unroll
            for (int j = 0; j < 4; j++) {
                int k4 = ks * 4 + j * 128;   // warp-wide contiguous 512B chunks
                float4 w0 = *(const float4*)&Wsm[(u_w * 4 + 0) * 512 + k4];
                float4 w1 = *(const float4*)&Wsm[(u_w * 4 + 1) * 512 + k4];
                float4 w2 = *(const float4*)&Wsm[(u_w * 4 + 2) * 512 + k4];
                float4 w3 = *(const float4*)&Wsm[(u_w * 4 + 3) * 512 + k4];
#pragma unroll
                for (int b = 0; b < 8; b++) {
                    float4 hb = *(const float4*)&Hsm[b * 512 + k4];
                    acc[0][b] = fmaf(w0.x, hb.x, fmaf(w0.y, hb.y, fmaf(w0.z, hb.z, fmaf(w0.w, hb.w, acc[0][b]))));
                    acc[1][b] = fmaf(w1.x, hb.x, fmaf(w1.y, hb.y, fmaf(w1.z, hb.z, fmaf(w1.w, hb.w, acc[1][b]))));
                    acc[2][b] = fmaf(w2.x, hb.x, fmaf(w2.y, hb.y, fmaf(w2.z, hb.z, fmaf(w2.w, hb.w, acc[2][b]))));
                    acc[3][b] = fmaf(w3.x, hb.x, fmaf(w3.y, hb.y, fmaf(w3.z, hb.z, fmaf(w3.w, hb.w, acc[3][b]))));
                }
            }
            // scatter partials: row (u_w*32 + g*8 + b), padded stride 33
#pragma unroll
            for (int g = 0; g < 4; g++)
#pragma unroll
                for (int b = 0; b < 8; b++)
                    Red[(u_w * 32 + g * 8 + b) * 33 + ks] = acc[g][b];
        }
        __syncthreads();

        if (tid < 64) {
            float s[4];
#pragma unroll
            for (int g = 0; g < 4; g++) {
                float t = 0.f;
                if (step > 0) {
                    const float* rp = Red + (u_a * 32 + g * 8 + b_a) * 33;
#pragma unroll
                    for (int k2 = 0; k2 < 32; k2++) t += rp[k2];
                }
                s[g] = t + Gv[g];
            }
            float ig = sigm_f(s[0]);
            float fg = sigm_f(s[1]);
            float gg = tanh_f(s[2]);
            float og = sigm_f(s[3]);
            c = fmaf(fg, c, ig * gg);
            float h = og * tanh_f(c);

            g_h[dir * (BB * HH) + b_a * HH + hg] = h;
            out[((size_t)t_eff * BB + b_a) * (2 * HH) + dir * HH + hg] = h;
        }

        if (step < TT - 1) {
            __threadfence();          // publish h writes at GPU scope
            __syncthreads();
            if (tid == 0) {
                unsigned g0  = atomicAdd(&g_gen, 0u);
                unsigned old = atomicAdd(&g_cnt, 1u);
                if (old == NCTA - 1) {
                    atomicExch(&g_cnt, 0u);   // reset before release
                    __threadfence();
                    atomicAdd(&g_gen, 1u);    // release (monotone across replays)
                } else {
                    while (atomicAdd(&g_gen, 0u) == g0) __nanosleep(32);
                }
                __threadfence();          // acquire side
            }
            __syncthreads();
        }
    }
}

// =================================================================================
extern "C" void kernel_launch(void* const* d_in, const int* in_sizes, int n_in,
                              void* d_out, int out_size)
{
    const float* X     = (const float*)d_in[0];
    const float* Wih_f = (const float*)d_in[1];
    const float* Whh_f = (const float*)d_in[2];
    const float* bih_f = (const float*)d_in[3];
    const float* bhh_f = (const float*)d_in[4];
    const float* Wih_b = (const float*)d_in[5];
    const float* Whh_b = (const float*)d_in[6];
    const float* bih_b = (const float*)d_in[7];
    const float* bhh_b = (const float*)d_in[8];
    float* out = (float*)d_out;

    cudaFuncSetAttribute(lstm_recur, cudaFuncAttributeMaxDynamicSharedMemorySize,
                         SM_FLOATS * sizeof(float));

    dim3 ggrid(G4H / 128, MTOT / 128, 2);   // (16, 128, 2)
    gates_gemm<<<ggrid, 256>>>(X, Wih_f, bih_f, bhh_f, Wih_b, bih_b, bhh_b);

    lstm_recur<<<NCTA, RTHREADS, SM_FLOATS * sizeof(float)>>>(Whh_f, Whh_b, out);
}

// round 7
// speedup vs baseline: 1.0714x; 1.0714x over previous
#include <cuda_runtime.h>
#include <cstdint>

// Problem dims
#define TT   2048
#define BB   8
#define II   512
#define HH   512
#define G4H  2048
#define MTOT (BB*TT)     // 16384

// Recurrence persistent-kernel config
#define NCTA      128    // 2 dirs * 64 CTAs; 8 h-units per CTA (1 unit per warp)
#define RTHREADS  256

// ---------------- static device scratch (no allocations allowed) ----------------
// Precomputed input-gate projections: G[dir][m][4H], m = b*T + t  (256 MiB)
__device__ __align__(16) float g_G[(size_t)2 * MTOT * G4H];
// Ping-pong hidden state: [buf][dir][b][H]  (step s writes buf s&1, step s+1 reads it)
__device__ __align__(16) float g_h[2][2 * BB * HH];
// Grid barrier state (gen monotone across graph replays; cnt returns to 0)
__device__ unsigned g_cnt;
__device__ unsigned g_gen;

// =================================================================================
// Kernel 1: gates GEMM.  G[dir][m][n] = sum_k X[m][k]*Wih_dir[n][k] + bih[n]+bhh[n]
// Tiles: BM=128, BN=128, BK=8, 256 threads, 8x8 per thread.  (unchanged)
// =================================================================================
__global__ __launch_bounds__(256) void gates_gemm(
    const float* __restrict__ X,
    const float* __restrict__ Wf, const float* __restrict__ bif, const float* __restrict__ bhf,
    const float* __restrict__ Wb, const float* __restrict__ bib, const float* __restrict__ bhb)
{
    const int dir = blockIdx.z;
    const float* __restrict__ W  = dir ? Wb  : Wf;
    const float* __restrict__ b1 = dir ? bib : bif;
    const float* __restrict__ b2 = dir ? bhb : bhf;

    __shared__ __align__(16) float As[8][128];
    __shared__ __align__(16) float Bs[8][128];

    const int tid  = threadIdx.x;
    const int m0   = blockIdx.y * 128;
    const int n0   = blockIdx.x * 128;
    const int tx   = tid & 15;          // n-frag
    const int ty   = tid >> 4;          // m-frag
    const int lrow = tid >> 1;          // 0..127
    const int lk   = (tid & 1) * 4;     // 0 or 4

    float acc[8][8];
#pragma unroll
    for (int i = 0; i < 8; i++)
#pragma unroll
        for (int j = 0; j < 8; j++) acc[i][j] = 0.f;

    const float* Ag = X + (size_t)(m0 + lrow) * II + lk;
    const float* Bg = W + (size_t)(n0 + lrow) * II + lk;

    float4 a = *(const float4*)(Ag);
    float4 b = *(const float4*)(Bg);

    for (int k0 = 0; k0 < II; k0 += 8) {
        __syncthreads();
        As[lk + 0][lrow] = a.x; As[lk + 1][lrow] = a.y;
        As[lk + 2][lrow] = a.z; As[lk + 3][lrow] = a.w;
        Bs[lk + 0][lrow] = b.x; Bs[lk + 1][lrow] = b.y;
        Bs[lk + 2][lrow] = b.z; Bs[lk + 3][lrow] = b.w;
        __syncthreads();
        if (k0 + 8 < II) {
            a = *(const float4*)(Ag + k0 + 8);
            b = *(const float4*)(Bg + k0 + 8);
        }
#pragma unroll
        for (int k = 0; k < 8; k++) {
            float4 a0 = *(const float4*)&As[k][ty * 8];
            float4 a1 = *(const float4*)&As[k][ty * 8 + 4];
            float4 b0 = *(const float4*)&Bs[k][tx * 8];
            float4 b1v = *(const float4*)&Bs[k][tx * 8 + 4];
            float ar[8] = {a0.x, a0.y, a0.z, a0.w, a1.x, a1.y, a1.z, a1.w};
            float br[8] = {b0.x, b0.y, b0.z, b0.w, b1v.x, b1v.y, b1v.z, b1v.w};
#pragma unroll
            for (int i = 0; i < 8; i++)
#pragma unroll
                for (int j = 0; j < 8; j++)
                    acc[i][j] = fmaf(ar[i], br[j], acc[i][j]);
        }
    }

    const int nb = n0 + tx * 8;
    float bias[8];
#pragma unroll
    for (int j = 0; j < 8; j++) bias[j] = b1[nb + j] + b2[nb + j];

#pragma unroll
    for (int i = 0; i < 8; i++) {
        size_t row = (size_t)dir * MTOT + (size_t)(m0 + ty * 8 + i);
        float* op = g_G + row * G4H + nb;
        float4 o0, o1;
        o0.x = acc[i][0] + bias[0]; o0.y = acc[i][1] + bias[1];
        o0.z = acc[i][2] + bias[2]; o0.w = acc[i][3] + bias[3];
        o1.x = acc[i][4] + bias[4]; o1.y = acc[i][5] + bias[5];
        o1.z = acc[i][6] + bias[6]; o1.w = acc[i][7] + bias[7];
        *(float4*)op = o0;
        *(float4*)(op + 4) = o1;
    }
}

// =================================================================================
// Kernel 2: persistent bidirectional LSTM recurrence (rewritten).
//  - 128 CTAs x 256 threads; warp w owns hidden unit (h0 + w), all 4 gate rows.
//  - Whh slice (16 float4 per lane) lives in REGISTERS for the whole kernel.
//  - Dot uses packed fma.rn.f32x2 (FFMA2): 256 packed FMA per lane per step.
//  - K-split-32 partials reduced by a register-halving warp butterfly (31 shfl),
//    leaving lane l = b*4+g holding gate sum (g, b) for its warp's unit.
//  - 4-shfl gate gather; lanes with g==0 hold cell state c and do activations.
//  - Ping-pong h buffers in gmem kill the cross-CTA WAR race; h staged to SMEM
//    once per CTA per step with __ldcg (L1 bypass).
// =================================================================================
__device__ __forceinline__ float sigm_f(float x) {
    return __fdividef(1.f, 1.f + __expf(-x));
}
__device__ __forceinline__ float tanh_f(float x) {
    float ax = fabsf(x);
    float e  = __expf(-2.f * ax);               // in (0,1], never overflows
    float r  = __fdividef(1.f - e, 1.f + e);
    return x < 0.f ? -r : r;
}
__device__ __forceinline__ void ffma2(unsigned long long& d,
                                      unsigned long long a, unsigned long long b) {
    asm("fma.rn.f32x2 %0, %1, %2, %0;" : "+l"(d) : "l"(a), "l"(b));
}

__global__ __launch_bounds__(RTHREADS, 1) void lstm_recur(
    const float* __restrict__ Whh_f,
    const float* __restrict__ Whh_b,
    float* __restrict__ out)
{
    __shared__ __align__(16) float Hsm[BB * HH];   // 16 KB h stage

    const int tid = threadIdx.x;
    const int wid = tid >> 5;       // hidden unit within CTA (0..7)
    const int ks  = tid & 31;       // lane = K-slice index
    const int cta = blockIdx.x;
    const int dir = cta >> 6;
    const int h0  = (cta & 63) * 8;
    const int hg  = h0 + wid;       // this warp's global hidden unit
    const float* __restrict__ Whh = dir ? Whh_b : Whh_f;

    // ---- persistent weights in registers: wr[g][j] = float4 of row (g*512+hg)
    //      at float offset ks*4 + j*128 (the lane's K-slice), as two packed f32x2.
    unsigned long long wr[4][4][2];
#pragma unroll
    for (int g = 0; g < 4; g++)
#pragma unroll
        for (int j = 0; j < 4; j++) {
            const float* p = Whh + (size_t)(g * HH + hg) * HH + ks * 4 + j * 128;
            ulonglong2 v = *(const ulonglong2*)p;   // 16B aligned, coalesced
            wr[g][j][0] = v.x; wr[g][j][1] = v.y;
        }

    const int  b_l = ks >> 2;        // lane's output batch   (r = b*4+g)
    const int  g_l = ks & 3;         // lane's output gate
    const bool act = (g_l == 0);     // activation lanes (8 per warp)

    float c = 0.f;                   // cell state for (unit=wid, batch=b_l), act lanes

    for (int step = 0; step < TT; step++) {
        const int t_eff = dir ? (TT - 1 - step) : step;

        // prefetch this lane's precomputed input-gate value (latency hidden by dot)
        float Gv = __ldg(g_G + ((size_t)dir * MTOT + (size_t)b_l * TT + t_eff) * G4H
                              + g_l * HH + hg);

        float stot;
        if (step > 0) {
            // ---- stage h (previous step's buffer) into SMEM, L1-bypassed ----
            const float* hp = g_h[(step + 1) & 1] + dir * (BB * HH);
#pragma unroll
            for (int v = 0; v < 4; v++) {
                int q = (tid + v * 256) * 4;        // float offset, 16B aligned
                float4 hv = __ldcg((const float4*)(hp + q));
                *(float4*)&Hsm[q] = hv;
            }
            __syncthreads();

            // ---- packed dot: acc[r] (r=b*4+g) holds 2 packed K-partials ----
            unsigned long long acc[32];
#pragma unroll
            for (int r = 0; r < 32; r++) acc[r] = 0ull;

#pragma unroll
            for (int j = 0; j < 4; j++) {
#pragma unroll
                for (int b = 0; b < 8; b++) {
                    ulonglong2 hb = *(const ulonglong2*)&Hsm[b * HH + ks * 4 + j * 128];
#pragma unroll
                    for (int g = 0; g < 4; g++) {
                        ffma2(acc[b * 4 + g], wr[g][j][0], hb.x);
                        ffma2(acc[b * 4 + g], wr[g][j][1], hb.y);
                    }
                }
            }

            // ---- collapse packed halves ----
            float s[32];
#pragma unroll
            for (int r = 0; r < 32; r++) {
                float lo = __uint_as_float((unsigned)acc[r]);
                float hi = __uint_as_float((unsigned)(acc[r] >> 32));
                s[r] = lo + hi;
            }

            // ---- register-halving butterfly: lane l ends holding sum of s[l] ----
#pragma unroll
            for (int lvl = 0; lvl < 5; lvl++) {
                const int  off = 16 >> lvl;
                const bool up  = (ks & off) != 0;
#pragma unroll
                for (int r = 0; r < (16 >> lvl); r++) {
                    float send = up ? s[r] : s[r + off];
                    float keep = up ? s[r + off] : s[r];
                    float recv = __shfl_xor_sync(0xffffffffu, send, off);
                    s[r] = keep + recv;
                }
            }
            stot = s[0] + Gv;
        } else {
            stot = Gv;              // h0 = 0: gates are input projection only
        }

        // ---- gather the 4 gates of (unit, b_l) onto the act lane ----
        const int base = ks & ~3;
        float v0 = __shfl_sync(0xffffffffu, stot, base);
        float v1 = __shfl_sync(0xffffffffu, stot, base + 1);
        float v2 = __shfl_sync(0xffffffffu, stot, base + 2);
        float v3 = __shfl_sync(0xffffffffu, stot, base + 3);

        if (act) {
            float ig = sigm_f(v0);
            float fg = sigm_f(v1);
            float gg = tanh_f(v2);
            float og = sigm_f(v3);
            c = fmaf(fg, c, ig * gg);
            float h = og * tanh_f(c);

            g_h[step & 1][dir * (BB * HH) + b_l * HH + hg] = h;   // next step's input
            out[((size_t)t_eff * BB + b_l) * (2 * HH) + dir * HH + hg] = h;
        }

        // ---- grid barrier (release: gen increment; pollers: volatile L2 load) ----
        if (step < TT - 1) {
            __syncthreads();
            if (tid == 0) {
                __threadfence();
                unsigned g0  = *(volatile unsigned*)&g_gen;
                unsigned old = atomicAdd(&g_cnt, 1u);
                if (old == NCTA - 1) {
                    atomicExch(&g_cnt, 0u);     // reset before release
                    __threadfence();
                    atomicAdd(&g_gen, 1u);      // release (monotone across replays)
                } else {
                    while (*(volatile unsigned*)&g_gen == g0) __nanosleep(16);
                }
                __threadfence();                // acquire
            }
            __syncthreads();
        }
    }
}

// =================================================================================
extern "C" void kernel_launch(void* const* d_in, const int* in_sizes, int n_in,
                              void* d_out, int out_size)
{
    const float* X     = (const float*)d_in[0];
    const float* Wih_f = (const float*)d_in[1];
    const float* Whh_f = (const float*)d_in[2];
    const float* bih_f = (const float*)d_in[3];
    const float* bhh_f = (const float*)d_in[4];
    const float* Wih_b = (const float*)d_in[5];
    const float* Whh_b = (const float*)d_in[6];
    const float* bih_b = (const float*)d_in[7];
    const float* bhh_b = (const float*)d_in[8];
    float* out = (float*)d_out;

    dim3 ggrid(G4H / 128, MTOT / 128, 2);   // (16, 128, 2)
    gates_gemm<<<ggrid, 256>>>(X, Wih_f, bih_f, bhh_f, Wih_b, bih_b, bhh_b);

    lstm_recur<<<NCTA, RTHREADS>>>(Whh_f, Whh_b, out);
}

// round 10
// speedup vs baseline: 1.0910x; 1.0184x over previous
#include <cuda_runtime.h>
#include <cstdint>

// Problem dims
#define TT   2048
#define BB   8
#define II   512
#define HH   512
#define G4H  2048
#define MTOT (BB*TT)     // 16384

// Recurrence persistent-kernel config
#define NCTA      128    // 2 dirs * 64 CTAs; 8 h-units per CTA (1 unit per warp)
#define RTHREADS  256

// ---------------- static device scratch (no allocations allowed) ----------------
// Precomputed input-gate projections: G[dir][m][4H], m = b*T + t  (256 MiB)
__device__ __align__(16) float g_G[(size_t)2 * MTOT * G4H];
// Ping-pong hidden state: [buf][dir][b][H]
__device__ __align__(16) float g_h[2][2 * BB * HH];
// Distributed barrier: per-CTA monotone flags (32B padded) + monotone release word.
// All counters only ever increase -> graph-replay safe; bases re-read each replay.
__device__ unsigned g_flag[NCTA * 8];
__device__ unsigned g_gen2;

__device__ __forceinline__ void ffma2(unsigned long long& d,
                                      unsigned long long a, unsigned long long b) {
    asm("fma.rn.f32x2 %0, %1, %2, %0;" : "+l"(d) : "l"(a), "l"(b));
}
__device__ __forceinline__ unsigned long long dup2(float a) {
    unsigned long long r;
    asm("mov.b64 %0, {%1, %1};" : "=l"(r) : "f"(a));
    return r;
}

// =================================================================================
// Kernel 1: gates GEMM.  G[dir][m][n] = sum_k X[m][k]*Wih_dir[n][k] + bih[n]+bhh[n]
// BM=128, BN=128, BK=16, 256 threads, 8x8 per thread, packed-f32x2 accumulators.
// =================================================================================
__global__ __launch_bounds__(256) void gates_gemm(
    const float* __restrict__ X,
    const float* __restrict__ Wf, const float* __restrict__ bif, const float* __restrict__ bhf,
    const float* __restrict__ Wb, const float* __restrict__ bib, const float* __restrict__ bhb)
{
    const int dir = blockIdx.z;
    const float* __restrict__ W  = dir ? Wb  : Wf;
    const float* __restrict__ bA = dir ? bib : bif;
    const float* __restrict__ bB = dir ? bhb : bhf;

    __shared__ __align__(16) float As[16][128];
    __shared__ __align__(16) float Bs[16][128];

    const int tid  = threadIdx.x;
    const int m0   = blockIdx.y * 128;
    const int n0   = blockIdx.x * 128;
    const int tx   = tid & 15;          // n-frag
    const int ty   = tid >> 4;          // m-frag
    const int lrow = tid >> 1;          // 0..127
    const int lk   = (tid & 1) * 4;     // 0 or 4

    // acc2[i][jj] packs output cols {2jj, 2jj+1} for row i of the 8x8 microtile
    unsigned long long acc2[8][4];
#pragma unroll
    for (int i = 0; i < 8; i++)
#pragma unroll
        for (int j = 0; j < 4; j++) acc2[i][j] = 0ull;

    const float* Ag = X + (size_t)(m0 + lrow) * II + lk;
    const float* Bg = W + (size_t)(n0 + lrow) * II + lk;

    float4 a0 = *(const float4*)(Ag);
    float4 a1 = *(const float4*)(Ag + 8);
    float4 b0 = *(const float4*)(Bg);
    float4 b1 = *(const float4*)(Bg + 8);

    for (int k0 = 0; k0 < II; k0 += 16) {
        __syncthreads();
        As[lk + 0][lrow] = a0.x;  As[lk + 1][lrow] = a0.y;
        As[lk + 2][lrow] = a0.z;  As[lk + 3][lrow] = a0.w;
        As[lk + 8][lrow] = a1.x;  As[lk + 9][lrow] = a1.y;
        As[lk +10][lrow] = a1.z;  As[lk +11][lrow] = a1.w;
        Bs[lk + 0][lrow] = b0.x;  Bs[lk + 1][lrow] = b0.y;
        Bs[lk + 2][lrow] = b0.z;  Bs[lk + 3][lrow] = b0.w;
        Bs[lk + 8][lrow] = b1.x;  Bs[lk + 9][lrow] = b1.y;
        Bs[lk +10][lrow] = b1.z;  Bs[lk +11][lrow] = b1.w;
        __syncthreads();
        if (k0 + 16 < II) {
            a0 = *(const float4*)(Ag + k0 + 16);
            a1 = *(const float4*)(Ag + k0 + 24);
            b0 = *(const float4*)(Bg + k0 + 16);
            b1 = *(const float4*)(Bg + k0 + 24);
        }
#pragma unroll
        for (int k = 0; k < 16; k++) {
            float4 av0 = *(const float4*)&As[k][ty * 8];
            float4 av1 = *(const float4*)&As[k][ty * 8 + 4];
            ulonglong2 bp0 = *(const ulonglong2*)&Bs[k][tx * 8];
            ulonglong2 bp1 = *(const ulonglong2*)&Bs[k][tx * 8 + 4];
            float ar[8] = {av0.x, av0.y, av0.z, av0.w, av1.x, av1.y, av1.z, av1.w};
#pragma unroll
            for (int i = 0; i < 8; i++) {
                unsigned long long ad = dup2(ar[i]);
                ffma2(acc2[i][0], bp0.x, ad);
                ffma2(acc2[i][1], bp0.y, ad);
                ffma2(acc2[i][2], bp1.x, ad);
                ffma2(acc2[i][3], bp1.y, ad);
            }
        }
    }

    const int nb = n0 + tx * 8;
    float bias[8];
#pragma unroll
    for (int j = 0; j < 8; j++) bias[j] = bA[nb + j] + bB[nb + j];

#pragma unroll
    for (int i = 0; i < 8; i++) {
        size_t row = (size_t)dir * MTOT + (size_t)(m0 + ty * 8 + i);
        float* op = g_G + row * G4H + nb;
        float c[8];
#pragma unroll
        for (int jj = 0; jj < 4; jj++) {
            c[2 * jj]     = __uint_as_float((unsigned)acc2[i][jj])         + bias[2 * jj];
            c[2 * jj + 1] = __uint_as_float((unsigned)(acc2[i][jj] >> 32)) + bias[2 * jj + 1];
        }
        float4 o0 = {c[0], c[1], c[2], c[3]};
        float4 o1 = {c[4], c[5], c[6], c[7]};
        *(float4*)op       = o0;
        *(float4*)(op + 4) = o1;
    }
}

// =================================================================================
// Kernel 2: persistent bidirectional LSTM recurrence.
//  - 128 CTAs x 256 threads; warp w owns hidden unit (h0 + w), all 4 gate rows.
//  - Whh slice in REGISTERS; dot via packed fma.rn.f32x2.
//  - Register-halving warp butterfly reduction; act lanes do cell update.
//  - NEW: distributed-flag grid barrier (no same-address atomic serialization,
//    parallel detection by CTA0, tight polls, no nanosleep).
// =================================================================================
__device__ __forceinline__ float sigm_f(float x) {
    return __fdividef(1.f, 1.f + __expf(-x));
}
__device__ __forceinline__ float tanh_f(float x) {
    float ax = fabsf(x);
    float e  = __expf(-2.f * ax);               // in (0,1], never overflows
    float r  = __fdividef(1.f - e, 1.f + e);
    return x < 0.f ? -r : r;
}

__global__ __launch_bounds__(RTHREADS, 1) void lstm_recur(
    const float* __restrict__ Whh_f,
    const float* __restrict__ Whh_b,
    float* __restrict__ out)
{
    __shared__ __align__(16) float Hsm[BB * HH];   // 16 KB h stage

    const int tid = threadIdx.x;
    const int wid = tid >> 5;       // hidden unit within CTA (0..7)
    const int ks  = tid & 31;       // lane = K-slice index
    const int cta = blockIdx.x;
    const int dir = cta >> 6;
    const int h0  = (cta & 63) * 8;
    const int hg  = h0 + wid;       // this warp's global hidden unit
    const float* __restrict__ Whh = dir ? Whh_b : Whh_f;

    // ---- persistent weights in registers ----
    unsigned long long wr[4][4][2];
#pragma unroll
    for (int g = 0; g < 4; g++)
#pragma unroll
        for (int j = 0; j < 4; j++) {
            const float* p = Whh + (size_t)(g * HH + hg) * HH + ks * 4 + j * 128;
            ulonglong2 v = *(const ulonglong2*)p;
            wr[g][j][0] = v.x; wr[g][j][1] = v.y;
        }

    // ---- barrier bases (owner-stable reads; uniform across CTAs at replay start;
    //      ordered before this CTA's first flag write by the fence in the barrier) ----
    const unsigned base_f = *(volatile unsigned*)&g_flag[cta * 8];
    const unsigned base_g = *(volatile unsigned*)&g_gen2;

    const int  b_l = ks >> 2;        // lane's output batch   (r = b*4+g)
    const int  g_l = ks & 3;         // lane's output gate
    const bool act = (g_l == 0);     // activation lanes (8 per warp)

    float c = 0.f;

    for (int step = 0; step < TT; step++) {
        const int t_eff = dir ? (TT - 1 - step) : step;

        // prefetch this lane's precomputed input-gate value
        float Gv = __ldg(g_G + ((size_t)dir * MTOT + (size_t)b_l * TT + t_eff) * G4H
                              + g_l * HH + hg);

        float stot;
        if (step > 0) {
            // ---- stage h (previous step's buffer) into SMEM, L1-bypassed ----
            const float* hp = g_h[(step + 1) & 1] + dir * (BB * HH);
#pragma unroll
            for (int v = 0; v < 4; v++) {
                int q = (tid + v * 256) * 4;
                float4 hv = __ldcg((const float4*)(hp + q));
                *(float4*)&Hsm[q] = hv;
            }
            __syncthreads();

            // ---- packed dot ----
            unsigned long long acc[32];
#pragma unroll
            for (int r = 0; r < 32; r++) acc[r] = 0ull;

#pragma unroll
            for (int j = 0; j < 4; j++) {
#pragma unroll
                for (int b = 0; b < 8; b++) {
                    ulonglong2 hb = *(const ulonglong2*)&Hsm[b * HH + ks * 4 + j * 128];
#pragma unroll
                    for (int g = 0; g < 4; g++) {
                        ffma2(acc[b * 4 + g], wr[g][j][0], hb.x);
                        ffma2(acc[b * 4 + g], wr[g][j][1], hb.y);
                    }
                }
            }

            float s[32];
#pragma unroll
            for (int r = 0; r < 32; r++) {
                float lo = __uint_as_float((unsigned)acc[r]);
                float hi = __uint_as_float((unsigned)(acc[r] >> 32));
                s[r] = lo + hi;
            }

            // ---- register-halving butterfly ----
#pragma unroll
            for (int lvl = 0; lvl < 5; lvl++) {
                const int  off = 16 >> lvl;
                const bool up  = (ks & off) != 0;
#pragma unroll
                for (int r = 0; r < (16 >> lvl); r++) {
                    float send = up ? s[r] : s[r + off];
                    float keep = up ? s[r + off] : s[r];
                    float recv = __shfl_xor_sync(0xffffffffu, send, off);
                    s[r] = keep + recv;
                }
            }
            stot = s[0] + Gv;
        } else {
            stot = Gv;
        }

        // ---- gather the 4 gates of (unit, b_l) onto the act lane ----
        const int base = ks & ~3;
        float v0 = __shfl_sync(0xffffffffu, stot, base);
        float v1 = __shfl_sync(0xffffffffu, stot, base + 1);
        float v2 = __shfl_sync(0xffffffffu, stot, base + 2);
        float v3 = __shfl_sync(0xffffffffu, stot, base + 3);

        if (act) {
            float ig = sigm_f(v0);
            float fg = sigm_f(v1);
            float gg = tanh_f(v2);
            float og = sigm_f(v3);
            c = fmaf(fg, c, ig * gg);
            float h = og * tanh_f(c);

            g_h[step & 1][dir * (BB * HH) + b_l * HH + hg] = h;
            out[((size_t)t_eff * BB + b_l) * (2 * HH) + dir * HH + hg] = h;
        }

        // ---- distributed-flag grid barrier ----
        if (step < TT - 1) {
            const unsigned tgt_f = base_f + (unsigned)step + 1u;
            const unsigned tgt_g = base_g + (unsigned)step + 1u;
            __syncthreads();                 // all h writes of this CTA done
            if (cta == 0) {
                if (tid == 0) {
                    __threadfence();         // publish h (gpu scope)
                    *(volatile unsigned*)&g_flag[0] = tgt_f;  // keep flags in lockstep
                } else if (tid < NCTA) {
                    while (*(volatile unsigned*)&g_flag[tid * 8] < tgt_f) {}
                    __threadfence();         // acquire: order observed h before our reads
                }
                __syncthreads();             // detection complete
                if (tid == 0) {
                    __threadfence();
                    *(volatile unsigned*)&g_gen2 = tgt_g;     // release
                }
                // no further sync: CTA0 threads already ordered by the detect bar
            } else {
                if (tid == 0) {
                    __threadfence();         // publish h (gpu scope)
                    *(volatile unsigned*)&g_flag[cta * 8] = tgt_f;   // arrive
                    while (*(volatile unsigned*)&g_gen2 < tgt_g) {}  // wait release
                    __threadfence();         // acquire
                }
                __syncthreads();
            }
        }
    }
}

// =================================================================================
extern "C" void kernel_launch(void* const* d_in, const int* in_sizes, int n_in,
                              void* d_out, int out_size)
{
    const float* X     = (const float*)d_in[0];
    const float* Wih_f = (const float*)d_in[1];
    const float* Whh_f = (const float*)d_in[2];
    const float* bih_f = (const float*)d_in[3];
    const float* bhh_f = (const float*)d_in[4];
    const float* Wih_b = (const float*)d_in[5];
    const float* Whh_b = (const float*)d_in[6];
    const float* bih_b = (const float*)d_in[7];
    const float* bhh_b = (const float*)d_in[8];
    float* out = (float*)d_out;

    dim3 ggrid(G4H / 128, MTOT / 128, 2);   // (16, 128, 2)
    gates_gemm<<<ggrid, 256>>>(X, Wih_f, bih_f, bhh_f, Wih_b, bih_b, bhh_b);

    lstm_recur<<<NCTA, RTHREADS>>>(Whh_f, Whh_b, out);
}